// round 8
// baseline (speedup 1.0000x reference)
#include <cuda_runtime.h>
#include <math.h>

#define B 4
#define N 64
#define T 256
#define H 256
#define L 5
#define TOPK 8
#define BT (B*T)

#define RB4 4           // rows per block in GEMM kernels
#define KK 8            // k-tile
#define NT (H/KK)       // 32 tiles

// k_dots tiling
#define TB 32           // t-tile
#define NG 8            // peers per block

__constant__ int c_lags[L] = {1, 5, 10, 21, 30};

// -------- scratch (device globals: no allocation allowed) --------
__device__ float g_W[H*H];      // wq^T @ wk
__device__ float g_btil[H];     // bq @ wk
__device__ float g_v[H];        // wq^T @ bk
__device__ float g_c0;          // bq . bk
__device__ float g_wvT[H*H];
__device__ float g_w1T[H*H];
__device__ float g_w2T[H*H];
__device__ float g_Qt[BT*H];    // Q tilde
__device__ float g_c[BT];       // Q . bk per row
__device__ float g_lg[BT*N*L];  // full logits
__device__ float g_agg[BT*H];   // weighted sum of selected peer rows
__device__ float g_sw[BT];      // sum of weights

// ---- barrier-free GEMM, 2 rows per thread. Thread (j, xoff) accumulates rows
// [xoff, xoff+2) for column j. Weights streamed via coalesced LDG with 4-deep
// register prefetch; activations transposed in smem [H][RB4] (broadcast LDS).
__device__ __forceinline__ void gemm2(const float* __restrict__ Wg,
                                      const float* __restrict__ XT,
                                      float* acc, int j, int xoff) {
    float wb[4][KK];
    #pragma unroll
    for (int p = 0; p < 4; p++)
        #pragma unroll
        for (int hh = 0; hh < KK; hh++) wb[p][hh] = Wg[(p*KK + hh)*H + j];
    #pragma unroll 2
    for (int kt = 0; kt < NT; kt++) {
        int p = kt & 3;
        float w[KK];
        #pragma unroll
        for (int hh = 0; hh < KK; hh++) w[hh] = wb[p][hh];
        if (kt + 4 < NT) {
            #pragma unroll
            for (int hh = 0; hh < KK; hh++)
                wb[p][hh] = Wg[((kt+4)*KK + hh)*H + j];
        }
        #pragma unroll
        for (int hh = 0; hh < KK; hh++) {
            float ww = w[hh];
            float2 x = *(const float2*)&XT[(kt*KK + hh)*RB4 + xoff];
            acc[0] += x.x*ww; acc[1] += x.y*ww;
        }
    }
}

// =============== prep: W = wq^T wk, biases folded, transposes ===============
__global__ void k_prep(const float* __restrict__ wq, const float* __restrict__ wk,
                       const float* __restrict__ bq, const float* __restrict__ bk,
                       const float* __restrict__ wv, const float* __restrict__ w1,
                       const float* __restrict__ w2) {
    int bidx = blockIdx.x;
    int j = threadIdx.x;
    if (bidx < H) {
        int h = bidx;
        __shared__ float s_wq[H];
        s_wq[j] = wq[j*H + h];
        __syncthreads();
        float acc = 0.f;
        #pragma unroll 4
        for (int m = 0; m < H; m++) acc += s_wq[m] * wk[m*H + j];
        g_W[h*H + j]   = acc;
        g_wvT[h*H + j] = wv[j*H + h];
        g_w1T[h*H + j] = w1[j*H + h];
        g_w2T[h*H + j] = w2[j*H + h];
    } else if (bidx == H) {
        float acc = 0.f;
        for (int m = 0; m < H; m++) acc += bq[m] * wk[m*H + j];
        g_btil[j] = acc;
    } else if (bidx == H + 1) {
        float acc = 0.f;
        for (int m = 0; m < H; m++) acc += wq[m*H + j] * bk[m];
        g_v[j] = acc;
    } else {
        if (j < 32) {
            float s = 0.f;
            for (int i = j; i < H; i += 32) s += bq[i] * bk[i];
            for (int off = 16; off; off >>= 1) s += __shfl_down_sync(0xffffffffu, s, off);
            if (j == 0) g_c0 = s;
        }
    }
}

// ========= Qtilde = target_h @ W + btil ; c = target_h . v + c0 =============
// 512 threads: thread = (col j = tid&255, half = tid>>8 -> rows half*2..+2)
__global__ void k_qtilde(const float* __restrict__ x) {
    __shared__ float s_x[H*RB4];        // transposed input [H][RB4]
    __shared__ float s_part[16][2];
    int r0 = blockIdx.x * RB4;
    int tid = threadIdx.x;
    int j = tid & 255;
    int xoff = (tid >> 8) * 2;
    int wid = tid >> 5, lane = tid & 31;

    float v[2];
    #pragma unroll
    for (int r = 0; r < 2; r++) v[r] = x[(r0 + xoff + r)*H + j];
    *(float2*)&s_x[j*RB4 + xoff] = make_float2(v[0], v[1]);

    float gv = g_v[j];
    #pragma unroll
    for (int r = 0; r < 2; r++) {
        float s = v[r] * gv;
        for (int off = 16; off; off >>= 1) s += __shfl_down_sync(0xffffffffu, s, off);
        if (lane == 0) s_part[wid][r] = s;
    }
    __syncthreads();
    if (tid < RB4) {                    // row = tid; half hf = tid>>1
        int hf = tid >> 1, rs = tid & 1;
        float s = g_c0;
        #pragma unroll
        for (int w = 0; w < 8; w++) s += s_part[hf*8 + w][rs];
        g_c[r0 + tid] = s;
    }

    float acc[2];
    float bt = g_btil[j];
    acc[0] = bt; acc[1] = bt;
    gemm2(g_W, s_x, acc, j, xoff);
    #pragma unroll
    for (int r = 0; r < 2; r++) g_Qt[(r0 + xoff + r)*H + j] = acc[r];
}

// ===== k_dots: logits for a (b, 32-t tile, 8-peer group). Each peer row is
// loaded once and dotted against up to 5 staged Q rows (lag diagonal reuse).
// 512 threads; explicit nl-outer / tp-inner loops with row prefetch.
__global__ void k_dots(const float* __restrict__ peer,
                       const int* __restrict__ mask) {
    extern __shared__ float sm[];
    float* s_q  = sm;                   // [TB][H]
    float* s_lg = sm + TB*H;            // [TB][NG][L]
    float* s_c  = s_lg + TB*NG*L;       // [TB]
    int*   s_mi = (int*)(s_c + TB);     // [NG]

    int bid = blockIdx.x;
    int ng = bid & 7;
    int tt = (bid >> 3) & 7;            // 8 t-tiles of 32
    int b  = bid >> 6;
    int t0 = tt * TB;
    int n0 = ng * NG;
    int tid = threadIdx.x;              // 512
    int wid = tid >> 5, lane = tid & 31;

    {
        const float4* src = (const float4*)&g_Qt[(b*T + t0)*H];
        float4* dst = (float4*)s_q;
        for (int i = tid; i < TB*H/4; i += 512) dst[i] = src[i];
        for (int i = tid; i < TB*NG*L; i += 512) s_lg[i] = -INFINITY;
        if (tid < TB) s_c[tid] = g_c[b*T + t0 + tid];
        if (tid < NG) s_mi[tid] = mask[b*N + n0 + tid];
    }
    __syncthreads();

    int tp_lo = t0 - 30; if (tp_lo < 0) tp_lo = 0;
    int tp_hi = t0 + TB - 2;

    for (int nl = 0; nl < NG; nl++) {
        if (!s_mi[nl]) continue;
        const float4* base = (const float4*)(peer + ((size_t)((b*N + n0 + nl)*T)) * H);
        int tp = tp_lo + wid;
        if (tp > tp_hi) continue;
        // prefetch first row
        float4 c0 = base[tp*64 + lane];
        float4 c1 = base[tp*64 + 32 + lane];
        while (tp <= tp_hi) {
            int tpn = tp + 16;
            float4 p0, p1;
            if (tpn <= tp_hi) {         // prefetch next before the shfl chain
                p0 = base[tpn*64 + lane];
                p1 = base[tpn*64 + 32 + lane];
            }
            float s[L]; int tl[L];
            #pragma unroll
            for (int l = 0; l < L; l++) {
                tl[l] = tp + c_lags[l] - t0;
                s[l] = 0.f;
                if ((unsigned)tl[l] < TB) {
                    const float4* q4 = (const float4*)&s_q[tl[l]*H];
                    float4 q0 = q4[lane];
                    float4 q1 = q4[lane + 32];
                    s[l] = c0.x*q0.x + c0.y*q0.y + c0.z*q0.z + c0.w*q0.w
                         + c1.x*q1.x + c1.y*q1.y + c1.z*q1.z + c1.w*q1.w;
                }
            }
            #pragma unroll
            for (int off = 16; off; off >>= 1) {
                #pragma unroll
                for (int l = 0; l < L; l++)
                    s[l] += __shfl_down_sync(0xffffffffu, s[l], off);
            }
            if (lane == 0) {
                #pragma unroll
                for (int l = 0; l < L; l++)
                    if ((unsigned)tl[l] < TB)
                        s_lg[(tl[l]*NG + nl)*L + l] = (s[l] + s_c[tl[l]]) * 0.0625f;
            }
            tp = tpn; c0 = p0; c1 = p1;
        }
    }
    __syncthreads();

    for (int i = tid; i < TB*NG*L; i += 512) {
        int trow = i / (NG*L);
        int rem = i - trow*(NG*L);
        g_lg[(size_t)(b*T + t0 + trow)*(N*L) + n0*L + rem] = s_lg[i];
    }
}

// ===== k_topk: per (b,t): parallel top-8 over 320 logits, softmax, aggregate
__global__ void k_topk(const float* __restrict__ peer) {
    __shared__ float s_l[N*L];
    __shared__ float s_cv[32];
    __shared__ int   s_ci[32];
    __shared__ float swt[TOPK];
    __shared__ int   sidx[TOPK];
    int bt = blockIdx.x;
    int b = bt >> 8;
    int t = bt & 255;
    int tid = threadIdx.x;          // 128 threads
    int wid = tid >> 5, lane = tid & 31;

    for (int i = tid; i < N*L; i += 128) s_l[i] = g_lg[(size_t)bt*(N*L) + i];
    __syncthreads();

    // phase 1: each warp takes top-8 of its contiguous 80-logit chunk
    {
        int base = wid * 80;
        for (int k = 0; k < TOPK; k++) {
            float bv = -INFINITY; int bi = 0x7fffffff;
            #pragma unroll
            for (int it = 0; it < 3; it++) {
                int i = base + lane + it*32;
                if (i < base + 80) {
                    float v = s_l[i];
                    if (v > bv || (v == bv && i < bi)) { bv = v; bi = i; }
                }
            }
            #pragma unroll
            for (int off = 16; off; off >>= 1) {
                float ov = __shfl_down_sync(0xffffffffu, bv, off);
                int   oi = __shfl_down_sync(0xffffffffu, bi, off);
                if (ov > bv || (ov == bv && oi < bi)) { bv = ov; bi = oi; }
            }
            bi = __shfl_sync(0xffffffffu, bi, 0);
            bv = __shfl_sync(0xffffffffu, bv, 0);
            if (lane == 0) { s_cv[wid*8 + k] = bv; s_ci[wid*8 + k] = bi; s_l[bi] = -INFINITY; }
            __syncwarp();
        }
    }
    __syncthreads();

    // phase 2: warp 0 merges 32 candidates -> global top-8, softmax
    if (wid == 0) {
        float cv = s_cv[lane];
        int   ci = s_ci[lane];
        float vals[TOPK];
        #pragma unroll
        for (int k = 0; k < TOPK; k++) {
            float bv = cv; int bi = ci;
            #pragma unroll
            for (int off = 16; off; off >>= 1) {
                float ov = __shfl_down_sync(0xffffffffu, bv, off);
                int   oi = __shfl_down_sync(0xffffffffu, bi, off);
                if (ov > bv || (ov == bv && oi < bi)) { bv = ov; bi = oi; }
            }
            bi = __shfl_sync(0xffffffffu, bi, 0);
            bv = __shfl_sync(0xffffffffu, bv, 0);
            vals[k] = bv;
            if (lane == 0) sidx[k] = bi;
            if (ci == bi) { cv = -INFINITY; ci = 0x7fffffff; }
        }
        if (lane == 0) {
            float m = -INFINITY;
            bool allinf = true;
            float safe[TOPK];
            #pragma unroll
            for (int k = 0; k < TOPK; k++) {
                bool ii = isinf(vals[k]);
                allinf = allinf && ii;
                safe[k] = ii ? -1e9f : vals[k];
                if (safe[k] > m) m = safe[k];
            }
            float sw_ = 0.f;
            if (allinf) {
                #pragma unroll
                for (int k = 0; k < TOPK; k++) swt[k] = 0.f;
            } else {
                float e[TOPK]; float tot = 0.f;
                #pragma unroll
                for (int k = 0; k < TOPK; k++) { e[k] = expf(safe[k] - m); tot += e[k]; }
                #pragma unroll
                for (int k = 0; k < TOPK; k++) { float w = e[k] / tot; swt[k] = w; sw_ += w; }
            }
            g_sw[bt] = sw_;
        }
    }
    __syncthreads();

    float acc0 = 0.f, acc1 = 0.f;
    #pragma unroll
    for (int k = 0; k < TOPK; k++) {
        float w = swt[k];
        if (w != 0.f) {
            int d = sidx[k];
            int n = d / L, l = d - n*L;
            int tp = t - c_lags[l];
            const float* row = peer + ((size_t)((b*N + n)*T + tp)) * H;
            acc0 += w * row[tid];
            acc1 += w * row[tid + 128];
        }
    }
    g_agg[bt*H + tid]       = acc0;
    g_agg[bt*H + tid + 128] = acc1;
}

// ===== cs_y = agg@wv^T + sw*bv ; FFN(elu) ; residual ; LayerNorm ; out ======
// 512 threads, RB4=4 rows/block: thread = (col j, half -> rows half*2..+2)
__global__ void k_ffn(const float* __restrict__ bv, const float* __restrict__ b1,
                      const float* __restrict__ b2, const float* __restrict__ gamma,
                      const float* __restrict__ beta, float* __restrict__ out) {
    __shared__ float s_xa[H*RB4];
    __shared__ float s_xb[H*RB4];
    __shared__ float s_sw[RB4];
    __shared__ float s_ps[16][2];
    __shared__ float s_pq[16][2];
    __shared__ float s_mu[RB4], s_rs[RB4];

    int r0 = blockIdx.x * RB4;
    int tid = threadIdx.x;
    int j = tid & 255;
    int xoff = (tid >> 8) * 2;
    int wid = tid >> 5, lane = tid & 31;

    {
        float v[2];
        #pragma unroll
        for (int r = 0; r < 2; r++) v[r] = g_agg[(r0 + xoff + r)*H + j];
        *(float2*)&s_xa[j*RB4 + xoff] = make_float2(v[0], v[1]);
    }
    if (tid < RB4) s_sw[tid] = g_sw[r0 + tid];
    __syncthreads();

    // GEMM1: cs = agg @ wv^T + sw*bv
    float cs[2];
    {
        float bvj = bv[j];
        #pragma unroll
        for (int r = 0; r < 2; r++) cs[r] = s_sw[xoff + r] * bvj;
        gemm2(g_wvT, s_xa, cs, j, xoff);
    }
    *(float2*)&s_xb[j*RB4 + xoff] = make_float2(cs[0], cs[1]);
    __syncthreads();

    // GEMM2: hidden = elu(cs @ w1^T + b1)
    float hd[2];
    {
        float b1j = b1[j];
        hd[0] = b1j; hd[1] = b1j;
        gemm2(g_w1T, s_xb, hd, j, xoff);
        #pragma unroll
        for (int r = 0; r < 2; r++) hd[r] = hd[r] > 0.f ? hd[r] : expm1f(hd[r]);
    }
    __syncthreads();       // all reads of s_xa (GEMM1) done before overwrite
    *(float2*)&s_xa[j*RB4 + xoff] = make_float2(hd[0], hd[1]);
    __syncthreads();

    // GEMM3: y = cs + hidden @ w2^T + b2
    float y[2];
    {
        float b2j = b2[j];
        #pragma unroll
        for (int r = 0; r < 2; r++) y[r] = b2j + cs[r];
        gemm2(g_w2T, s_xa, y, j, xoff);
    }

    // LayerNorm
    #pragma unroll
    for (int r = 0; r < 2; r++) {
        float s = y[r], q = y[r]*y[r];
        for (int off = 16; off; off >>= 1) {
            s += __shfl_down_sync(0xffffffffu, s, off);
            q += __shfl_down_sync(0xffffffffu, q, off);
        }
        if (lane == 0) { s_ps[wid][r] = s; s_pq[wid][r] = q; }
    }
    __syncthreads();
    if (tid < RB4) {
        int hf = tid >> 1, rs = tid & 1;
        float s = 0.f, q = 0.f;
        #pragma unroll
        for (int w = 0; w < 8; w++) { s += s_ps[hf*8 + w][rs]; q += s_pq[hf*8 + w][rs]; }
        float mu = s * (1.f/H);
        float var = q * (1.f/H) - mu*mu;
        s_mu[tid] = mu;
        s_rs[tid] = rsqrtf(var + 1e-5f);
    }
    __syncthreads();
    float gj = gamma[j], bj = beta[j];
    #pragma unroll
    for (int r = 0; r < 2; r++)
        out[(r0 + xoff + r)*H + j] = (y[r] - s_mu[xoff + r]) * s_rs[xoff + r] * gj + bj;
}

extern "C" void kernel_launch(void* const* d_in, const int* in_sizes, int n_in,
                              void* d_out, int out_size) {
    const float* target_h = (const float*)d_in[0];
    const float* peer_h   = (const float*)d_in[1];
    const int*   peer_mask = (const int*)d_in[2];
    const float* wq = (const float*)d_in[3];
    const float* bq = (const float*)d_in[4];
    const float* wk = (const float*)d_in[5];
    const float* bk = (const float*)d_in[6];
    const float* wv = (const float*)d_in[7];
    const float* bv = (const float*)d_in[8];
    const float* w1 = (const float*)d_in[9];
    const float* b1 = (const float*)d_in[10];
    const float* w2 = (const float*)d_in[11];
    const float* b2 = (const float*)d_in[12];
    const float* gamma = (const float*)d_in[13];
    const float* beta  = (const float*)d_in[14];
    float* out = (float*)d_out;

    const int DOTS_SMEM = (TB*H + TB*NG*L + TB + NG + 8) * 4;
    cudaFuncSetAttribute(k_dots, cudaFuncAttributeMaxDynamicSharedMemorySize, DOTS_SMEM);

    k_prep<<<H + 3, 256>>>(wq, wk, bq, bk, wv, w1, w2);
    k_qtilde<<<BT/RB4, 512>>>(target_h);
    k_dots<<<B * (T/TB) * (N/NG), 512, DOTS_SMEM>>>(peer_h, peer_mask);
    k_topk<<<BT, 128>>>(peer_h);
    k_ffn<<<BT/RB4, 512>>>(bv, b1, b2, gamma, beta, out);
}

// round 9
// speedup vs baseline: 1.4405x; 1.4405x over previous
#include <cuda_runtime.h>
#include <math.h>

#define B 4
#define N 64
#define T 256
#define H 256
#define L 5
#define TOPK 8
#define BT (B*T)

#define RB 8            // rows per block in GEMM kernels
#define KK 8            // k-tile
#define NT (H/KK)       // 32 tiles

__constant__ int c_lags[L] = {1, 5, 10, 21, 30};

// -------- scratch (device globals: no allocation allowed) --------
__device__ float g_W[H*H];      // wq^T @ wk
__device__ float g_btil[H];     // bq @ wk
__device__ float g_v[H];        // wq^T @ bk
__device__ float g_c0;          // bq . bk
__device__ float g_wvT[H*H];
__device__ float g_w1T[H*H];
__device__ float g_w2T[H*H];
__device__ float g_Qt[BT*H];    // Q tilde
__device__ float g_c[BT];       // Q . bk per row
__device__ float g_agg[BT*H];   // weighted sum of selected peer rows
__device__ float g_sw[BT];      // sum of weights

// ---- barrier-free GEMM, 4 rows per thread. Thread (j, xoff) accumulates rows
// [xoff..xoff+4) for column j. Weights streamed via coalesced LDG with 4-deep
// register prefetch (distance covers L2 latency); activations transposed in
// smem [H][RB], read via broadcast LDS.128.
__device__ __forceinline__ void gemm_ldg4(const float* __restrict__ Wg,
                                          const float* __restrict__ XT,
                                          float* acc, int j, int xoff) {
    float wb[4][KK];
    #pragma unroll
    for (int p = 0; p < 4; p++)
        #pragma unroll
        for (int hh = 0; hh < KK; hh++) wb[p][hh] = Wg[(p*KK + hh)*H + j];
    #pragma unroll 2
    for (int kt = 0; kt < NT; kt++) {
        int p = kt & 3;
        float w[KK];
        #pragma unroll
        for (int hh = 0; hh < KK; hh++) w[hh] = wb[p][hh];
        if (kt + 4 < NT) {
            #pragma unroll
            for (int hh = 0; hh < KK; hh++)
                wb[p][hh] = Wg[((kt+4)*KK + hh)*H + j];
        }
        #pragma unroll
        for (int hh = 0; hh < KK; hh++) {
            float ww = w[hh];
            float4 x0 = *(const float4*)&XT[(kt*KK + hh)*RB + xoff];
            acc[0] += x0.x*ww; acc[1] += x0.y*ww;
            acc[2] += x0.z*ww; acc[3] += x0.w*ww;
        }
    }
}

// =============== prep: W = wq^T wk, biases folded, transposes ===============
__global__ void k_prep(const float* __restrict__ wq, const float* __restrict__ wk,
                       const float* __restrict__ bq, const float* __restrict__ bk,
                       const float* __restrict__ wv, const float* __restrict__ w1,
                       const float* __restrict__ w2) {
    int bidx = blockIdx.x;
    int j = threadIdx.x;
    if (bidx < H) {
        int h = bidx;
        __shared__ float s_wq[H];
        s_wq[j] = wq[j*H + h];
        __syncthreads();
        float acc = 0.f;
        #pragma unroll 4
        for (int m = 0; m < H; m++) acc += s_wq[m] * wk[m*H + j];
        g_W[h*H + j]   = acc;
        g_wvT[h*H + j] = wv[j*H + h];
        g_w1T[h*H + j] = w1[j*H + h];
        g_w2T[h*H + j] = w2[j*H + h];
    } else if (bidx == H) {
        float acc = 0.f;
        for (int m = 0; m < H; m++) acc += bq[m] * wk[m*H + j];
        g_btil[j] = acc;
    } else if (bidx == H + 1) {
        float acc = 0.f;
        for (int m = 0; m < H; m++) acc += wq[m*H + j] * bk[m];
        g_v[j] = acc;
    } else {
        if (j < 32) {
            float s = 0.f;
            for (int i = j; i < H; i += 32) s += bq[i] * bk[i];
            for (int off = 16; off; off >>= 1) s += __shfl_down_sync(0xffffffffu, s, off);
            if (j == 0) g_c0 = s;
        }
    }
}

// ========= Qtilde = target_h @ W + btil ; c = target_h . v + c0 =============
// 512 threads: thread = (col j = tid&255, half = tid>>8 -> rows half*4..+4)
__global__ void k_qtilde(const float* __restrict__ x) {
    __shared__ float s_x[H*RB];         // transposed input [H][RB]
    __shared__ float s_part[16][4];
    int r0 = blockIdx.x * RB;
    int tid = threadIdx.x;
    int j = tid & 255;
    int xoff = (tid >> 8) * 4;
    int wid = tid >> 5, lane = tid & 31;

    float v[4];
    #pragma unroll
    for (int r = 0; r < 4; r++) v[r] = x[(r0 + xoff + r)*H + j];
    *(float4*)&s_x[j*RB + xoff] = make_float4(v[0], v[1], v[2], v[3]);

    float gv = g_v[j];
    #pragma unroll
    for (int r = 0; r < 4; r++) {
        float s = v[r] * gv;
        for (int off = 16; off; off >>= 1) s += __shfl_down_sync(0xffffffffu, s, off);
        if (lane == 0) s_part[wid][r] = s;
    }
    __syncthreads();
    if (tid < RB) {                     // row = tid; half hf = tid>>2
        int hf = tid >> 2, rs = tid & 3;
        float s = g_c0;
        #pragma unroll
        for (int w = 0; w < 8; w++) s += s_part[hf*8 + w][rs];
        g_c[r0 + tid] = s;
    }

    float acc[4];
    float bt = g_btil[j];
    #pragma unroll
    for (int r = 0; r < 4; r++) acc[r] = bt;
    gemm_ldg4(g_W, s_x, acc, j, xoff);
    #pragma unroll
    for (int r = 0; r < 4; r++) g_Qt[(r0 + xoff + r)*H + j] = acc[r];
}

// ===== k_logits (R2/R4 measured version): logits, mask, top-8, softmax, agg ==
__global__ void k_logits(const float* __restrict__ peer,
                         const int* __restrict__ mask) {
    int bt = blockIdx.x;
    int b = bt >> 8;          // T = 256
    int t = bt & 255;
    __shared__ float qrow[H];
    __shared__ float lg[N*L];
    __shared__ float swt[TOPK];
    __shared__ int   sidx[TOPK];
    __shared__ float scbt;
    int tid = threadIdx.x;
    qrow[tid] = g_Qt[bt*H + tid];
    if (tid == 0) scbt = g_c[bt];
    __syncthreads();
    float cbt = scbt;
    int wid = tid >> 5, lane = tid & 31;
    const float4* q4 = (const float4*)qrow;

    for (int d = wid; d < N*L; d += 8) {
        int n = d / L, l = d - n*L;
        int tp = t - c_lags[l];
        bool ok = (tp >= 0) && (mask[(b << 6) + n] != 0);
        float val;
        if (ok) {
            const float4* p4 = (const float4*)(peer + ((size_t)((b*N + n)*T + tp)) * H);
            float s = 0.f;
            #pragma unroll
            for (int i = 0; i < 2; i++) {
                float4 pv = p4[lane + 32*i];
                float4 qv = q4[lane + 32*i];
                s += pv.x*qv.x + pv.y*qv.y + pv.z*qv.z + pv.w*qv.w;
            }
            for (int off = 16; off; off >>= 1) s += __shfl_down_sync(0xffffffffu, s, off);
            val = (s + cbt) * 0.0625f;
        } else {
            val = -INFINITY;
        }
        if (lane == 0) lg[d] = val;
    }
    __syncthreads();

    if (wid == 0) {
        float vals[TOPK];
        for (int k = 0; k < TOPK; k++) {
            float bv = -INFINITY; int bi = 0x7fffffff;
            for (int i = lane; i < N*L; i += 32) {
                float v = lg[i];
                if (v > bv || (v == bv && i < bi)) { bv = v; bi = i; }
            }
            for (int off = 16; off; off >>= 1) {
                float ov = __shfl_down_sync(0xffffffffu, bv, off);
                int   oi = __shfl_down_sync(0xffffffffu, bi, off);
                if (ov > bv || (ov == bv && oi < bi)) { bv = ov; bi = oi; }
            }
            bi = __shfl_sync(0xffffffffu, bi, 0);
            bv = __shfl_sync(0xffffffffu, bv, 0);
            if (lane == 0) { sidx[k] = bi; vals[k] = bv; lg[bi] = -INFINITY; }
            __syncwarp();
        }
        if (lane == 0) {
            float m = -INFINITY;
            bool allinf = true;
            float safe[TOPK];
            #pragma unroll
            for (int k = 0; k < TOPK; k++) {
                bool ii = isinf(vals[k]);
                allinf = allinf && ii;
                safe[k] = ii ? -1e9f : vals[k];
                if (safe[k] > m) m = safe[k];
            }
            float sw_ = 0.f;
            if (allinf) {
                #pragma unroll
                for (int k = 0; k < TOPK; k++) swt[k] = 0.f;
            } else {
                float e[TOPK]; float tot = 0.f;
                #pragma unroll
                for (int k = 0; k < TOPK; k++) { e[k] = expf(safe[k] - m); tot += e[k]; }
                #pragma unroll
                for (int k = 0; k < TOPK; k++) { float w = e[k] / tot; swt[k] = w; sw_ += w; }
            }
            g_sw[bt] = sw_;
        }
    }
    __syncthreads();

    float acc = 0.f;
    #pragma unroll
    for (int k = 0; k < TOPK; k++) {
        float w = swt[k];
        if (w != 0.f) {
            int d = sidx[k];
            int n = d / L, l = d - n*L;
            int tp = t - c_lags[l];
            acc += w * peer[((size_t)((b*N + n)*T + tp)) * H + tid];
        }
    }
    g_agg[bt*H + tid] = acc;
}

// ===== cs_y = agg@wv^T + sw*bv ; FFN(elu) ; residual ; LayerNorm ; out ======
// 512 threads, grid=128, RB=8: thread = (col j, half -> rows half*4..+4)
__global__ void k_ffn(const float* __restrict__ bv, const float* __restrict__ b1,
                      const float* __restrict__ b2, const float* __restrict__ gamma,
                      const float* __restrict__ beta, float* __restrict__ out) {
    __shared__ float s_xa[H*RB];
    __shared__ float s_xb[H*RB];
    __shared__ float s_sw[RB];
    __shared__ float s_ps[16][4];
    __shared__ float s_pq[16][4];
    __shared__ float s_mu[RB], s_rs[RB];

    int r0 = blockIdx.x * RB;
    int tid = threadIdx.x;
    int j = tid & 255;
    int xoff = (tid >> 8) * 4;
    int wid = tid >> 5, lane = tid & 31;

    {
        float v[4];
        #pragma unroll
        for (int r = 0; r < 4; r++) v[r] = g_agg[(r0 + xoff + r)*H + j];
        *(float4*)&s_xa[j*RB + xoff] = make_float4(v[0], v[1], v[2], v[3]);
    }
    if (tid < RB) s_sw[tid] = g_sw[r0 + tid];
    __syncthreads();

    // GEMM1: cs = agg @ wv^T + sw*bv
    float cs[4];
    {
        float bvj = bv[j];
        #pragma unroll
        for (int r = 0; r < 4; r++) cs[r] = s_sw[xoff + r] * bvj;
        gemm_ldg4(g_wvT, s_xa, cs, j, xoff);
    }
    *(float4*)&s_xb[j*RB + xoff] = make_float4(cs[0], cs[1], cs[2], cs[3]);
    __syncthreads();

    // GEMM2: hidden = elu(cs @ w1^T + b1)
    float hd[4];
    {
        float b1j = b1[j];
        #pragma unroll
        for (int r = 0; r < 4; r++) hd[r] = b1j;
        gemm_ldg4(g_w1T, s_xb, hd, j, xoff);
        #pragma unroll
        for (int r = 0; r < 4; r++) hd[r] = hd[r] > 0.f ? hd[r] : expm1f(hd[r]);
    }
    __syncthreads();       // all reads of s_xa (GEMM1) done before overwrite
    *(float4*)&s_xa[j*RB + xoff] = make_float4(hd[0], hd[1], hd[2], hd[3]);
    __syncthreads();

    // GEMM3: y = cs + hidden @ w2^T + b2
    float y[4];
    {
        float b2j = b2[j];
        #pragma unroll
        for (int r = 0; r < 4; r++) y[r] = b2j + cs[r];
        gemm_ldg4(g_w2T, s_xa, y, j, xoff);
    }

    // LayerNorm
    #pragma unroll
    for (int r = 0; r < 4; r++) {
        float s = y[r], q = y[r]*y[r];
        for (int off = 16; off; off >>= 1) {
            s += __shfl_down_sync(0xffffffffu, s, off);
            q += __shfl_down_sync(0xffffffffu, q, off);
        }
        if (lane == 0) { s_ps[wid][r] = s; s_pq[wid][r] = q; }
    }
    __syncthreads();
    if (tid < RB) {
        int hf = tid >> 2, rs = tid & 3;
        float s = 0.f, q = 0.f;
        #pragma unroll
        for (int w = 0; w < 8; w++) { s += s_ps[hf*8 + w][rs]; q += s_pq[hf*8 + w][rs]; }
        float mu = s * (1.f/H);
        float var = q * (1.f/H) - mu*mu;
        s_mu[tid] = mu;
        s_rs[tid] = rsqrtf(var + 1e-5f);
    }
    __syncthreads();
    float gj = gamma[j], bj = beta[j];
    #pragma unroll
    for (int r = 0; r < 4; r++)
        out[(r0 + xoff + r)*H + j] = (y[r] - s_mu[xoff + r]) * s_rs[xoff + r] * gj + bj;
}

extern "C" void kernel_launch(void* const* d_in, const int* in_sizes, int n_in,
                              void* d_out, int out_size) {
    const float* target_h = (const float*)d_in[0];
    const float* peer_h   = (const float*)d_in[1];
    const int*   peer_mask = (const int*)d_in[2];
    const float* wq = (const float*)d_in[3];
    const float* bq = (const float*)d_in[4];
    const float* wk = (const float*)d_in[5];
    const float* bk = (const float*)d_in[6];
    const float* wv = (const float*)d_in[7];
    const float* bv = (const float*)d_in[8];
    const float* w1 = (const float*)d_in[9];
    const float* b1 = (const float*)d_in[10];
    const float* w2 = (const float*)d_in[11];
    const float* b2 = (const float*)d_in[12];
    const float* gamma = (const float*)d_in[13];
    const float* beta  = (const float*)d_in[14];
    float* out = (float*)d_out;

    k_prep<<<H + 3, 256>>>(wq, wk, bq, bk, wv, w1, w2);
    k_qtilde<<<BT/RB, 512>>>(target_h);
    k_logits<<<BT, 256>>>(peer_h, peer_mask);
    k_ffn<<<BT/RB, 512>>>(bv, b1, b2, gamma, beta, out);
}

// round 12
// speedup vs baseline: 1.5589x; 1.0822x over previous
#include <cuda_runtime.h>
#include <math.h>
#include <stdint.h>

#define B 4
#define N 64
#define T 256
#define H 256
#define L 5
#define TOPK 8
#define BT (B*T)

#define RB16 16         // rows per block in GEMM kernels
#define XPAD 20         // padded row stride in transposed smem (16B aligned, conflict-free)

__constant__ int c_lags[L] = {1, 5, 10, 21, 30};

// -------- scratch (device globals: no allocation allowed) --------
__device__ float g_W[H*H];      // wq^T @ wk
__device__ float g_btil[H];     // bq @ wk
__device__ float g_v[H];        // wq^T @ bk
__device__ float g_c0;          // bq . bk
__device__ float g_wvT[H*H];
__device__ float g_w1T[H*H];
__device__ float g_w2T[H*H];
__device__ float g_Qt[BT*H];    // Q tilde
__device__ float g_c[BT];       // Q . bk per row
__device__ float g_agg[BT*H];   // weighted sum of selected peer rows
__device__ float g_sw[BT];      // sum of weights

// ---- packed f32x2 helpers ----
__device__ __forceinline__ uint64_t pack2(float lo, float hi) {
    uint64_t r;
    asm("mov.b64 %0, {%1, %2};" : "=l"(r) : "f"(lo), "f"(hi));
    return r;
}
__device__ __forceinline__ void unpack2(uint64_t v, float& lo, float& hi) {
    asm("mov.b64 {%0, %1}, %2;" : "=f"(lo), "=f"(hi) : "l"(v));
}
__device__ __forceinline__ void ffma2(uint64_t& d, uint64_t a, uint64_t b) {
    asm("fma.rn.f32x2 %0, %1, %2, %0;" : "+l"(d) : "l"(a), "l"(b));
}

// ---- GEMM core: 16 rows/block, 256 threads (thread = output column j).
// acc: 8 packed f32x2 = 16 rows. XT: transposed activations [h*XPAD + r],
// read via 4 broadcast LDS.128. Weight column streamed via LDG, 2-deep
// (16-element) register prefetch.
__device__ __forceinline__ void gemm16(const float* __restrict__ Wg,
                                       const float* __restrict__ XT,
                                       uint64_t* acc, int j) {
    float wb[2][8];
    #pragma unroll
    for (int p = 0; p < 2; p++)
        #pragma unroll
        for (int hh = 0; hh < 8; hh++) wb[p][hh] = Wg[(p*8 + hh)*H + j];
    for (int kt = 0; kt < 32; kt++) {
        int cur = kt & 1;
        float w[8];
        #pragma unroll
        for (int hh = 0; hh < 8; hh++) w[hh] = wb[cur][hh];
        if (kt + 2 < 32) {
            #pragma unroll
            for (int hh = 0; hh < 8; hh++)
                wb[cur][hh] = Wg[((kt+2)*8 + hh)*H + j];
        }
        #pragma unroll
        for (int hh = 0; hh < 8; hh++) {
            uint64_t w2 = pack2(w[hh], w[hh]);
            const ulonglong2* xp = (const ulonglong2*)(XT + (size_t)(kt*8 + hh)*XPAD);
            ulonglong2 u0 = xp[0];
            ulonglong2 u1 = xp[1];
            ulonglong2 u2 = xp[2];
            ulonglong2 u3 = xp[3];
            ffma2(acc[0], u0.x, w2); ffma2(acc[1], u0.y, w2);
            ffma2(acc[2], u1.x, w2); ffma2(acc[3], u1.y, w2);
            ffma2(acc[4], u2.x, w2); ffma2(acc[5], u2.y, w2);
            ffma2(acc[6], u3.x, w2); ffma2(acc[7], u3.y, w2);
        }
    }
}

// =============== prep (R4 version): W = wq^T wk, biases, transposes =========
__global__ void k_prep(const float* __restrict__ wq, const float* __restrict__ wk,
                       const float* __restrict__ bq, const float* __restrict__ bk,
                       const float* __restrict__ wv, const float* __restrict__ w1,
                       const float* __restrict__ w2) {
    int bidx = blockIdx.x;
    int j = threadIdx.x;
    if (bidx < H) {
        int h = bidx;
        float acc = 0.f;
        for (int m = 0; m < H; m++) acc += wq[m*H + h] * wk[m*H + j];
        g_W[h*H + j]   = acc;
        g_wvT[h*H + j] = wv[j*H + h];
        g_w1T[h*H + j] = w1[j*H + h];
        g_w2T[h*H + j] = w2[j*H + h];
    } else if (bidx == H) {
        float acc = 0.f;
        for (int m = 0; m < H; m++) acc += bq[m] * wk[m*H + j];
        g_btil[j] = acc;
    } else if (bidx == H + 1) {
        float acc = 0.f;
        for (int m = 0; m < H; m++) acc += wq[m*H + j] * bk[m];
        g_v[j] = acc;
    } else {
        if (j < 32) {
            float s = 0.f;
            for (int i = j; i < H; i += 32) s += bq[i] * bk[i];
            for (int off = 16; off; off >>= 1) s += __shfl_down_sync(0xffffffffu, s, off);
            if (j == 0) g_c0 = s;
        }
    }
}

// ========= Qtilde = target_h @ W + btil ; c = target_h . v + c0 =============
// 256 threads, 16 rows/block, grid = 64.
__global__ void k_qtilde(const float* __restrict__ x) {
    __shared__ __align__(16) float s_x[H*XPAD];
    __shared__ float s_part[8][RB16];
    int r0 = blockIdx.x * RB16;
    int tid = threadIdx.x;
    int j = tid;
    int wid = tid >> 5, lane = tid & 31;

    float v[RB16];
    #pragma unroll
    for (int r = 0; r < RB16; r++) v[r] = x[(r0 + r)*H + j];
    // transposed store: s_x[j*XPAD + r], 4x STS.128 (base j*80B, 16B aligned)
    #pragma unroll
    for (int i = 0; i < 4; i++)
        *(float4*)&s_x[j*XPAD + 4*i] = make_float4(v[4*i], v[4*i+1], v[4*i+2], v[4*i+3]);

    // c = x . g_v + c0 per row
    float gv = g_v[j];
    #pragma unroll
    for (int r = 0; r < RB16; r++) {
        float s = v[r] * gv;
        for (int off = 16; off; off >>= 1) s += __shfl_down_sync(0xffffffffu, s, off);
        if (lane == 0) s_part[wid][r] = s;
    }
    __syncthreads();
    if (tid < RB16) {
        float s = g_c0;
        #pragma unroll
        for (int w = 0; w < 8; w++) s += s_part[w][tid];
        g_c[r0 + tid] = s;
    }

    uint64_t acc[8];
    float bt = g_btil[j];
    #pragma unroll
    for (int i = 0; i < 8; i++) acc[i] = pack2(bt, bt);
    gemm16(g_W, s_x, acc, j);
    #pragma unroll
    for (int i = 0; i < 8; i++) {
        float lo, hi;
        unpack2(acc[i], lo, hi);
        g_Qt[(r0 + 2*i    )*H + j] = lo;
        g_Qt[(r0 + 2*i + 1)*H + j] = hi;
    }
}

// ===== k_logits (R2/R4 measured): logits, mask, top-8, softmax, aggregate ===
__global__ void k_logits(const float* __restrict__ peer,
                         const int* __restrict__ mask) {
    int bt = blockIdx.x;
    int b = bt >> 8;          // T = 256
    int t = bt & 255;
    __shared__ float qrow[H];
    __shared__ float lg[N*L];
    __shared__ float swt[TOPK];
    __shared__ int   sidx[TOPK];
    __shared__ float scbt;
    int tid = threadIdx.x;
    qrow[tid] = g_Qt[bt*H + tid];
    if (tid == 0) scbt = g_c[bt];
    __syncthreads();
    float cbt = scbt;
    int wid = tid >> 5, lane = tid & 31;
    const float4* q4 = (const float4*)qrow;

    for (int d = wid; d < N*L; d += 8) {
        int n = d / L, l = d - n*L;
        int tp = t - c_lags[l];
        bool ok = (tp >= 0) && (mask[(b << 6) + n] != 0);
        float val;
        if (ok) {
            const float4* p4 = (const float4*)(peer + ((size_t)((b*N + n)*T + tp)) * H);
            float s = 0.f;
            #pragma unroll
            for (int i = 0; i < 2; i++) {
                float4 pv = p4[lane + 32*i];
                float4 qv = q4[lane + 32*i];
                s += pv.x*qv.x + pv.y*qv.y + pv.z*qv.z + pv.w*qv.w;
            }
            for (int off = 16; off; off >>= 1) s += __shfl_down_sync(0xffffffffu, s, off);
            val = (s + cbt) * 0.0625f;
        } else {
            val = -INFINITY;
        }
        if (lane == 0) lg[d] = val;
    }
    __syncthreads();

    if (wid == 0) {
        float vals[TOPK];
        for (int k = 0; k < TOPK; k++) {
            float bv = -INFINITY; int bi = 0x7fffffff;
            for (int i = lane; i < N*L; i += 32) {
                float v = lg[i];
                if (v > bv || (v == bv && i < bi)) { bv = v; bi = i; }
            }
            for (int off = 16; off; off >>= 1) {
                float ov = __shfl_down_sync(0xffffffffu, bv, off);
                int   oi = __shfl_down_sync(0xffffffffu, bi, off);
                if (ov > bv || (ov == bv && oi < bi)) { bv = ov; bi = oi; }
            }
            bi = __shfl_sync(0xffffffffu, bi, 0);
            bv = __shfl_sync(0xffffffffu, bv, 0);
            if (lane == 0) { sidx[k] = bi; vals[k] = bv; lg[bi] = -INFINITY; }
            __syncwarp();
        }
        if (lane == 0) {
            float m = -INFINITY;
            bool allinf = true;
            float safe[TOPK];
            #pragma unroll
            for (int k = 0; k < TOPK; k++) {
                bool ii = isinf(vals[k]);
                allinf = allinf && ii;
                safe[k] = ii ? -1e9f : vals[k];
                if (safe[k] > m) m = safe[k];
            }
            float sw_ = 0.f;
            if (allinf) {
                #pragma unroll
                for (int k = 0; k < TOPK; k++) swt[k] = 0.f;
            } else {
                float e[TOPK]; float tot = 0.f;
                #pragma unroll
                for (int k = 0; k < TOPK; k++) { e[k] = expf(safe[k] - m); tot += e[k]; }
                #pragma unroll
                for (int k = 0; k < TOPK; k++) { float w = e[k] / tot; swt[k] = w; sw_ += w; }
            }
            g_sw[bt] = sw_;
        }
    }
    __syncthreads();

    float acc = 0.f;
    #pragma unroll
    for (int k = 0; k < TOPK; k++) {
        float w = swt[k];
        if (w != 0.f) {
            int d = sidx[k];
            int n = d / L, l = d - n*L;
            int tp = t - c_lags[l];
            acc += w * peer[((size_t)((b*N + n)*T + tp)) * H + tid];
        }
    }
    g_agg[bt*H + tid] = acc;
}

// ===== cs_y = agg@wv^T + sw*bv ; FFN(elu) ; residual ; LayerNorm ; out ======
// 256 threads, 16 rows/block, grid = 64. acc in packed f32x2.
__global__ void k_ffn(const float* __restrict__ bv, const float* __restrict__ b1,
                      const float* __restrict__ b2, const float* __restrict__ gamma,
                      const float* __restrict__ beta, float* __restrict__ out) {
    __shared__ __align__(16) float s_x[H*XPAD];   // transposed activations
    __shared__ float s_sw[RB16];
    __shared__ float s_mu[RB16], s_rs[RB16];

    int r0 = blockIdx.x * RB16;
    int tid = threadIdx.x;
    int j = tid;
    int wid = tid >> 5, lane = tid & 31;

    // load agg (coalesced) and store transposed
    {
        float v[RB16];
        #pragma unroll
        for (int r = 0; r < RB16; r++) v[r] = g_agg[(r0 + r)*H + j];
        #pragma unroll
        for (int i = 0; i < 4; i++)
            *(float4*)&s_x[j*XPAD + 4*i] = make_float4(v[4*i], v[4*i+1], v[4*i+2], v[4*i+3]);
    }
    if (tid < RB16) s_sw[tid] = g_sw[r0 + tid];
    __syncthreads();

    // ---- GEMM1: cs = agg @ wv^T + sw*bv ----
    float cs[RB16];
    {
        uint64_t acc[8];
        float bvj = bv[j];
        #pragma unroll
        for (int i = 0; i < 8; i++) acc[i] = pack2(s_sw[2*i]*bvj, s_sw[2*i+1]*bvj);
        gemm16(g_wvT, s_x, acc, j);
        #pragma unroll
        for (int i = 0; i < 8; i++) unpack2(acc[i], cs[2*i], cs[2*i+1]);
    }
    __syncthreads();            // all GEMM1 reads of s_x done
    #pragma unroll
    for (int i = 0; i < 4; i++)
        *(float4*)&s_x[j*XPAD + 4*i] = make_float4(cs[4*i], cs[4*i+1], cs[4*i+2], cs[4*i+3]);
    __syncthreads();

    // ---- GEMM2: hidden = elu(cs @ w1^T + b1) ----
    float hd[RB16];
    {
        uint64_t acc[8];
        float b1j = b1[j];
        #pragma unroll
        for (int i = 0; i < 8; i++) acc[i] = pack2(b1j, b1j);
        gemm16(g_w1T, s_x, acc, j);
        #pragma unroll
        for (int i = 0; i < 8; i++) unpack2(acc[i], hd[2*i], hd[2*i+1]);
        #pragma unroll
        for (int r = 0; r < RB16; r++) hd[r] = hd[r] > 0.f ? hd[r] : expm1f(hd[r]);
    }
    __syncthreads();
    #pragma unroll
    for (int i = 0; i < 4; i++)
        *(float4*)&s_x[j*XPAD + 4*i] = make_float4(hd[4*i], hd[4*i+1], hd[4*i+2], hd[4*i+3]);
    __syncthreads();

    // ---- GEMM3: y = cs + hidden @ w2^T + b2 ----
    float y[RB16];
    {
        uint64_t acc[8];
        float b2j = b2[j];
        #pragma unroll
        for (int i = 0; i < 8; i++) acc[i] = pack2(b2j + cs[2*i], b2j + cs[2*i+1]);
        gemm16(g_w2T, s_x, acc, j);
        #pragma unroll
        for (int i = 0; i < 8; i++) unpack2(acc[i], y[2*i], y[2*i+1]);
    }

    // ---- LayerNorm: stash y in smem (reuse s_x as [r][256]), warp per 2 rows
    __syncthreads();            // all GEMM3 reads of s_x done
    float* s_y = s_x;           // 16*256 = 16K floats fits in H*XPAD
    #pragma unroll
    for (int r = 0; r < RB16; r++) s_y[r*H + j] = y[r];
    __syncthreads();
    {
        #pragma unroll
        for (int rr = 0; rr < 2; rr++) {
            int r = wid + rr*8;
            float s = 0.f, q = 0.f;
            #pragma unroll
            for (int k = 0; k < 8; k++) {
                float vv = s_y[r*H + lane + 32*k];
                s += vv; q += vv*vv;
            }
            for (int off = 16; off; off >>= 1) {
                s += __shfl_down_sync(0xffffffffu, s, off);
                q += __shfl_down_sync(0xffffffffu, q, off);
            }
            if (lane == 0) {
                float mu = s * (1.f/H);
                float var = q * (1.f/H) - mu*mu;
                s_mu[r] = mu;
                s_rs[r] = rsqrtf(var + 1e-5f);
            }
        }
    }
    __syncthreads();
    float gj = gamma[j], bj = beta[j];
    #pragma unroll
    for (int r = 0; r < RB16; r++)
        out[(r0 + r)*H + j] = (y[r] - s_mu[r]) * s_rs[r] * gj + bj;
}

extern "C" void kernel_launch(void* const* d_in, const int* in_sizes, int n_in,
                              void* d_out, int out_size) {
    const float* target_h = (const float*)d_in[0];
    const float* peer_h   = (const float*)d_in[1];
    const int*   peer_mask = (const int*)d_in[2];
    const float* wq = (const float*)d_in[3];
    const float* bq = (const float*)d_in[4];
    const float* wk = (const float*)d_in[5];
    const float* bk = (const float*)d_in[6];
    const float* wv = (const float*)d_in[7];
    const float* bv = (const float*)d_in[8];
    const float* w1 = (const float*)d_in[9];
    const float* b1 = (const float*)d_in[10];
    const float* w2 = (const float*)d_in[11];
    const float* b2 = (const float*)d_in[12];
    const float* gamma = (const float*)d_in[13];
    const float* beta  = (const float*)d_in[14];
    float* out = (float*)d_out;

    k_prep<<<H + 3, 256>>>(wq, wk, bq, bk, wv, w1, w2);
    k_qtilde<<<BT/RB16, 256>>>(target_h);
    k_logits<<<BT, 256>>>(peer_h, peer_mask);
    k_ffn<<<BT/RB16, 256>>>(bv, b1, b2, gamma, beta, out);
}

// round 13
// speedup vs baseline: 1.8882x; 1.2113x over previous
#include <cuda_runtime.h>
#include <math.h>
#include <stdint.h>

#define B 4
#define N 64
#define T 256
#define H 256
#define L 5
#define TOPK 8
#define BT (B*T)

#define RB16 16         // rows per block in GEMM kernels
#define XPAD 20         // padded row stride in transposed smem (16B aligned, conflict-free)

__constant__ int c_lags[L] = {1, 5, 10, 21, 30};

// -------- scratch (device globals: no allocation allowed) --------
__device__ float g_W[H*H];      // wq^T @ wk
__device__ float g_btil[H];     // bq @ wk
__device__ float g_v[H];        // wq^T @ bk
__device__ float g_c0;          // bq . bk
__device__ float g_wvT[H*H];
__device__ float g_w1T[H*H];
__device__ float g_w2T[H*H];
__device__ float g_Qt[BT*H];    // Q tilde
__device__ float g_c[BT];       // Q . bk per row
__device__ float g_agg[BT*H];   // weighted sum of selected peer rows
__device__ float g_sw[BT];      // sum of weights

// ---- packed f32x2 helpers ----
__device__ __forceinline__ uint64_t pack2(float lo, float hi) {
    uint64_t r;
    asm("mov.b64 %0, {%1, %2};" : "=l"(r) : "f"(lo), "f"(hi));
    return r;
}
__device__ __forceinline__ void unpack2(uint64_t v, float& lo, float& hi) {
    asm("mov.b64 {%0, %1}, %2;" : "=f"(lo), "=f"(hi) : "l"(v));
}
__device__ __forceinline__ void ffma2(uint64_t& d, uint64_t a, uint64_t b) {
    asm("fma.rn.f32x2 %0, %1, %2, %0;" : "+l"(d) : "l"(a), "l"(b));
}

// ---- GEMM core v2: 16 rows/block, 256 threads (thread = output column j).
// acc: 8 packed f32x2 = 16 rows. XT: transposed activations [h*XPAD + r].
// Explicit h-parity DOUBLE BUFFER on activations: while the 8 FFMA2 of
// element h execute, the 4 LDS.128 of element h+1 are in flight. Weight
// column streamed via LDG with 2-tile register prefetch.
__device__ __forceinline__ void gemm16(const float* __restrict__ Wg,
                                       const float* __restrict__ XT,
                                       uint64_t* acc, int j) {
    float wb[2][8];
    #pragma unroll
    for (int p = 0; p < 2; p++)
        #pragma unroll
        for (int hh = 0; hh < 8; hh++) wb[p][hh] = Wg[(p*8 + hh)*H + j];

    ulonglong2 xs[2][4];
    {
        const ulonglong2* xp = (const ulonglong2*)XT;     // h = 0
        #pragma unroll
        for (int i = 0; i < 4; i++) xs[0][i] = xp[i];
    }

    #pragma unroll 2
    for (int kt = 0; kt < 32; kt++) {
        int curb = kt & 1;
        float w[8];
        #pragma unroll
        for (int hh = 0; hh < 8; hh++) w[hh] = wb[curb][hh];
        if (kt + 2 < 32) {
            #pragma unroll
            for (int hh = 0; hh < 8; hh++)
                wb[curb][hh] = Wg[((kt+2)*8 + hh)*H + j];
        }
        #pragma unroll
        for (int hh = 0; hh < 8; hh++) {
            int h = kt*8 + hh;
            int cur = h & 1, nxt = cur ^ 1;
            int hn = (h + 1) & 255;       // wrap harmlessly at the end
            const ulonglong2* xp = (const ulonglong2*)(XT + (size_t)hn*XPAD);
            xs[nxt][0] = xp[0];
            xs[nxt][1] = xp[1];
            xs[nxt][2] = xp[2];
            xs[nxt][3] = xp[3];
            uint64_t w2 = pack2(w[hh], w[hh]);
            ffma2(acc[0], xs[cur][0].x, w2); ffma2(acc[1], xs[cur][0].y, w2);
            ffma2(acc[2], xs[cur][1].x, w2); ffma2(acc[3], xs[cur][1].y, w2);
            ffma2(acc[4], xs[cur][2].x, w2); ffma2(acc[5], xs[cur][2].y, w2);
            ffma2(acc[6], xs[cur][3].x, w2); ffma2(acc[7], xs[cur][3].y, w2);
        }
    }
}

// =============== prep (R4 version): W = wq^T wk, biases, transposes =========
__global__ void k_prep(const float* __restrict__ wq, const float* __restrict__ wk,
                       const float* __restrict__ bq, const float* __restrict__ bk,
                       const float* __restrict__ wv, const float* __restrict__ w1,
                       const float* __restrict__ w2) {
    int bidx = blockIdx.x;
    int j = threadIdx.x;
    if (bidx < H) {
        int h = bidx;
        float acc = 0.f;
        for (int m = 0; m < H; m++) acc += wq[m*H + h] * wk[m*H + j];
        g_W[h*H + j]   = acc;
        g_wvT[h*H + j] = wv[j*H + h];
        g_w1T[h*H + j] = w1[j*H + h];
        g_w2T[h*H + j] = w2[j*H + h];
    } else if (bidx == H) {
        float acc = 0.f;
        for (int m = 0; m < H; m++) acc += bq[m] * wk[m*H + j];
        g_btil[j] = acc;
    } else if (bidx == H + 1) {
        float acc = 0.f;
        for (int m = 0; m < H; m++) acc += wq[m*H + j] * bk[m];
        g_v[j] = acc;
    } else {
        if (j < 32) {
            float s = 0.f;
            for (int i = j; i < H; i += 32) s += bq[i] * bk[i];
            for (int off = 16; off; off >>= 1) s += __shfl_down_sync(0xffffffffu, s, off);
            if (j == 0) g_c0 = s;
        }
    }
}

// ========= Qtilde = target_h @ W + btil ; c = target_h . v + c0 =============
// 256 threads, 16 rows/block, grid = 64.
__global__ void __launch_bounds__(256) k_qtilde(const float* __restrict__ x) {
    __shared__ __align__(16) float s_x[H*XPAD];
    __shared__ float s_part[8][RB16];
    int r0 = blockIdx.x * RB16;
    int tid = threadIdx.x;
    int j = tid;
    int wid = tid >> 5, lane = tid & 31;

    float v[RB16];
    #pragma unroll
    for (int r = 0; r < RB16; r++) v[r] = x[(r0 + r)*H + j];
    #pragma unroll
    for (int i = 0; i < 4; i++)
        *(float4*)&s_x[j*XPAD + 4*i] = make_float4(v[4*i], v[4*i+1], v[4*i+2], v[4*i+3]);

    float gv = g_v[j];
    #pragma unroll
    for (int r = 0; r < RB16; r++) {
        float s = v[r] * gv;
        for (int off = 16; off; off >>= 1) s += __shfl_down_sync(0xffffffffu, s, off);
        if (lane == 0) s_part[wid][r] = s;
    }
    __syncthreads();
    if (tid < RB16) {
        float s = g_c0;
        #pragma unroll
        for (int w = 0; w < 8; w++) s += s_part[w][tid];
        g_c[r0 + tid] = s;
    }

    uint64_t acc[8];
    float bt = g_btil[j];
    #pragma unroll
    for (int i = 0; i < 8; i++) acc[i] = pack2(bt, bt);
    gemm16(g_W, s_x, acc, j);
    #pragma unroll
    for (int i = 0; i < 8; i++) {
        float lo, hi;
        unpack2(acc[i], lo, hi);
        g_Qt[(r0 + 2*i    )*H + j] = lo;
        g_Qt[(r0 + 2*i + 1)*H + j] = hi;
    }
}

// ===== k_logits (R2/R4 measured): logits, mask, top-8, softmax, aggregate ===
__global__ void k_logits(const float* __restrict__ peer,
                         const int* __restrict__ mask) {
    int bt = blockIdx.x;
    int b = bt >> 8;          // T = 256
    int t = bt & 255;
    __shared__ float qrow[H];
    __shared__ float lg[N*L];
    __shared__ float swt[TOPK];
    __shared__ int   sidx[TOPK];
    __shared__ float scbt;
    int tid = threadIdx.x;
    qrow[tid] = g_Qt[bt*H + tid];
    if (tid == 0) scbt = g_c[bt];
    __syncthreads();
    float cbt = scbt;
    int wid = tid >> 5, lane = tid & 31;
    const float4* q4 = (const float4*)qrow;

    for (int d = wid; d < N*L; d += 8) {
        int n = d / L, l = d - n*L;
        int tp = t - c_lags[l];
        bool ok = (tp >= 0) && (mask[(b << 6) + n] != 0);
        float val;
        if (ok) {
            const float4* p4 = (const float4*)(peer + ((size_t)((b*N + n)*T + tp)) * H);
            float s = 0.f;
            #pragma unroll
            for (int i = 0; i < 2; i++) {
                float4 pv = p4[lane + 32*i];
                float4 qv = q4[lane + 32*i];
                s += pv.x*qv.x + pv.y*qv.y + pv.z*qv.z + pv.w*qv.w;
            }
            for (int off = 16; off; off >>= 1) s += __shfl_down_sync(0xffffffffu, s, off);
            val = (s + cbt) * 0.0625f;
        } else {
            val = -INFINITY;
        }
        if (lane == 0) lg[d] = val;
    }
    __syncthreads();

    if (wid == 0) {
        float vals[TOPK];
        for (int k = 0; k < TOPK; k++) {
            float bv = -INFINITY; int bi = 0x7fffffff;
            for (int i = lane; i < N*L; i += 32) {
                float v = lg[i];
                if (v > bv || (v == bv && i < bi)) { bv = v; bi = i; }
            }
            for (int off = 16; off; off >>= 1) {
                float ov = __shfl_down_sync(0xffffffffu, bv, off);
                int   oi = __shfl_down_sync(0xffffffffu, bi, off);
                if (ov > bv || (ov == bv && oi < bi)) { bv = ov; bi = oi; }
            }
            bi = __shfl_sync(0xffffffffu, bi, 0);
            bv = __shfl_sync(0xffffffffu, bv, 0);
            if (lane == 0) { sidx[k] = bi; vals[k] = bv; lg[bi] = -INFINITY; }
            __syncwarp();
        }
        if (lane == 0) {
            float m = -INFINITY;
            bool allinf = true;
            float safe[TOPK];
            #pragma unroll
            for (int k = 0; k < TOPK; k++) {
                bool ii = isinf(vals[k]);
                allinf = allinf && ii;
                safe[k] = ii ? -1e9f : vals[k];
                if (safe[k] > m) m = safe[k];
            }
            float sw_ = 0.f;
            if (allinf) {
                #pragma unroll
                for (int k = 0; k < TOPK; k++) swt[k] = 0.f;
            } else {
                float e[TOPK]; float tot = 0.f;
                #pragma unroll
                for (int k = 0; k < TOPK; k++) { e[k] = expf(safe[k] - m); tot += e[k]; }
                #pragma unroll
                for (int k = 0; k < TOPK; k++) { float w = e[k] / tot; swt[k] = w; sw_ += w; }
            }
            g_sw[bt] = sw_;
        }
    }
    __syncthreads();

    float acc = 0.f;
    #pragma unroll
    for (int k = 0; k < TOPK; k++) {
        float w = swt[k];
        if (w != 0.f) {
            int d = sidx[k];
            int n = d / L, l = d - n*L;
            int tp = t - c_lags[l];
            acc += w * peer[((size_t)((b*N + n)*T + tp)) * H + tid];
        }
    }
    g_agg[bt*H + tid] = acc;
}

// ===== cs_y = agg@wv^T + sw*bv ; FFN(elu) ; residual ; LayerNorm ; out ======
// 256 threads, 16 rows/block, grid = 64. acc in packed f32x2.
__global__ void __launch_bounds__(256) k_ffn(
                      const float* __restrict__ bv, const float* __restrict__ b1,
                      const float* __restrict__ b2, const float* __restrict__ gamma,
                      const float* __restrict__ beta, float* __restrict__ out) {
    __shared__ __align__(16) float s_x[H*XPAD];   // transposed activations
    __shared__ float s_sw[RB16];
    __shared__ float s_mu[RB16], s_rs[RB16];

    int r0 = blockIdx.x * RB16;
    int tid = threadIdx.x;
    int j = tid;
    int wid = tid >> 5, lane = tid & 31;

    // load agg (coalesced) and store transposed
    {
        float v[RB16];
        #pragma unroll
        for (int r = 0; r < RB16; r++) v[r] = g_agg[(r0 + r)*H + j];
        #pragma unroll
        for (int i = 0; i < 4; i++)
            *(float4*)&s_x[j*XPAD + 4*i] = make_float4(v[4*i], v[4*i+1], v[4*i+2], v[4*i+3]);
    }
    if (tid < RB16) s_sw[tid] = g_sw[r0 + tid];
    __syncthreads();

    // ---- GEMM1: cs = agg @ wv^T + sw*bv ----
    float cs[RB16];
    {
        uint64_t acc[8];
        float bvj = bv[j];
        #pragma unroll
        for (int i = 0; i < 8; i++) acc[i] = pack2(s_sw[2*i]*bvj, s_sw[2*i+1]*bvj);
        gemm16(g_wvT, s_x, acc, j);
        #pragma unroll
        for (int i = 0; i < 8; i++) unpack2(acc[i], cs[2*i], cs[2*i+1]);
    }
    __syncthreads();            // all GEMM1 reads of s_x done
    #pragma unroll
    for (int i = 0; i < 4; i++)
        *(float4*)&s_x[j*XPAD + 4*i] = make_float4(cs[4*i], cs[4*i+1], cs[4*i+2], cs[4*i+3]);
    __syncthreads();

    // ---- GEMM2: hidden = elu(cs @ w1^T + b1) ----
    float hd[RB16];
    {
        uint64_t acc[8];
        float b1j = b1[j];
        #pragma unroll
        for (int i = 0; i < 8; i++) acc[i] = pack2(b1j, b1j);
        gemm16(g_w1T, s_x, acc, j);
        #pragma unroll
        for (int i = 0; i < 8; i++) unpack2(acc[i], hd[2*i], hd[2*i+1]);
        #pragma unroll
        for (int r = 0; r < RB16; r++) hd[r] = hd[r] > 0.f ? hd[r] : expm1f(hd[r]);
    }
    __syncthreads();
    #pragma unroll
    for (int i = 0; i < 4; i++)
        *(float4*)&s_x[j*XPAD + 4*i] = make_float4(hd[4*i], hd[4*i+1], hd[4*i+2], hd[4*i+3]);
    __syncthreads();

    // ---- GEMM3: y = cs + hidden @ w2^T + b2 ----
    float y[RB16];
    {
        uint64_t acc[8];
        float b2j = b2[j];
        #pragma unroll
        for (int i = 0; i < 8; i++) acc[i] = pack2(b2j + cs[2*i], b2j + cs[2*i+1]);
        gemm16(g_w2T, s_x, acc, j);
        #pragma unroll
        for (int i = 0; i < 8; i++) unpack2(acc[i], y[2*i], y[2*i+1]);
    }

    // ---- LayerNorm: stash y in smem (reuse s_x as [r][256]), warp per 2 rows
    __syncthreads();            // all GEMM3 reads of s_x done
    float* s_y = s_x;           // 16*256 = 4K floats fits in H*XPAD
    #pragma unroll
    for (int r = 0; r < RB16; r++) s_y[r*H + j] = y[r];
    __syncthreads();
    {
        #pragma unroll
        for (int rr = 0; rr < 2; rr++) {
            int r = wid + rr*8;
            float s = 0.f, q = 0.f;
            #pragma unroll
            for (int k = 0; k < 8; k++) {
                float vv = s_y[r*H + lane + 32*k];
                s += vv; q += vv*vv;
            }
            for (int off = 16; off; off >>= 1) {
                s += __shfl_down_sync(0xffffffffu, s, off);
                q += __shfl_down_sync(0xffffffffu, q, off);
            }
            if (lane == 0) {
                float mu = s * (1.f/H);
                float var = q * (1.f/H) - mu*mu;
                s_mu[r] = mu;
                s_rs[r] = rsqrtf(var + 1e-5f);
            }
        }
    }
    __syncthreads();
    float gj = gamma[j], bj = beta[j];
    #pragma unroll
    for (int r = 0; r < RB16; r++)
        out[(r0 + r)*H + j] = (y[r] - s_mu[r]) * s_rs[r] * gj + bj;
}

extern "C" void kernel_launch(void* const* d_in, const int* in_sizes, int n_in,
                              void* d_out, int out_size) {
    const float* target_h = (const float*)d_in[0];
    const float* peer_h   = (const float*)d_in[1];
    const int*   peer_mask = (const int*)d_in[2];
    const float* wq = (const float*)d_in[3];
    const float* bq = (const float*)d_in[4];
    const float* wk = (const float*)d_in[5];
    const float* bk = (const float*)d_in[6];
    const float* wv = (const float*)d_in[7];
    const float* bv = (const float*)d_in[8];
    const float* w1 = (const float*)d_in[9];
    const float* b1 = (const float*)d_in[10];
    const float* w2 = (const float*)d_in[11];
    const float* b2 = (const float*)d_in[12];
    const float* gamma = (const float*)d_in[13];
    const float* beta  = (const float*)d_in[14];
    float* out = (float*)d_out;

    k_prep<<<H + 3, 256>>>(wq, wk, bq, bk, wv, w1, w2);
    k_qtilde<<<BT/RB16, 256>>>(target_h);
    k_logits<<<BT, 256>>>(peer_h, peer_mask);
    k_ffn<<<BT/RB16, 256>>>(bv, b1, b2, gamma, beta, out);
}

// round 14
// speedup vs baseline: 2.2031x; 1.1667x over previous
#include <cuda_runtime.h>
#include <math.h>
#include <stdint.h>

#define B 4
#define N 64
#define T 256
#define H 256
#define L 5
#define TOPK 8
#define BT (B*T)

#define RB8 8           // rows per block in GEMM kernels
#define XP 12           // transposed-activation row stride (16B-aligned)
#define RP 9            // reduction buffer stride (conflict-free)

__constant__ int c_lags[L] = {1, 5, 10, 21, 30};

// -------- scratch (device globals: no allocation allowed) --------
__device__ float g_W[H*H];      // wq^T @ wk
__device__ float g_btil[H];     // bq @ wk
__device__ float g_v[H];        // wq^T @ bk
__device__ float g_c0;          // bq . bk
__device__ float g_wvT[H*H];
__device__ float g_w1T[H*H];
__device__ float g_w2T[H*H];
__device__ float g_Qt[BT*H];    // Q tilde
__device__ float g_c[BT];       // Q . bk per row
__device__ float g_agg[BT*H];   // weighted sum of selected peer rows
__device__ float g_sw[BT];      // sum of weights

// ---- packed f32x2 helpers ----
__device__ __forceinline__ uint64_t pack2(float lo, float hi) {
    uint64_t r;
    asm("mov.b64 %0, {%1, %2};" : "=l"(r) : "f"(lo), "f"(hi));
    return r;
}
__device__ __forceinline__ void unpack2(uint64_t v, float& lo, float& hi) {
    asm("mov.b64 {%0, %1}, %2;" : "=f"(lo), "=f"(hi) : "l"(v));
}
__device__ __forceinline__ void ffma2(uint64_t& d, uint64_t a, uint64_t b) {
    asm("fma.rn.f32x2 %0, %1, %2, %0;" : "+l"(d) : "l"(a), "l"(b));
}

// ---- GEMM core: 8 rows, 128-long k-range starting at k0.
// acc: 4 packed f32x2 = 8 rows. XT: transposed activations [h*XP + r].
// h-parity double buffer on activations (2 LDS.128 in flight while 4 FFMA2
// execute); weight column streamed via LDG with 2-tile register prefetch.
__device__ __forceinline__ void gemm8k(const float* __restrict__ Wg,
                                       const float* __restrict__ XT,
                                       uint64_t* acc, int j, int k0) {
    float wb[2][8];
    #pragma unroll
    for (int p = 0; p < 2; p++)
        #pragma unroll
        for (int hh = 0; hh < 8; hh++) wb[p][hh] = Wg[(k0 + p*8 + hh)*H + j];

    ulonglong2 xs[2][2];
    {
        const ulonglong2* xp = (const ulonglong2*)(XT + (size_t)k0*XP);
        xs[0][0] = xp[0]; xs[0][1] = xp[1];
    }
    #pragma unroll 2
    for (int kt = 0; kt < 16; kt++) {
        int curb = kt & 1;
        float w[8];
        #pragma unroll
        for (int hh = 0; hh < 8; hh++) w[hh] = wb[curb][hh];
        if (kt + 2 < 16) {
            #pragma unroll
            for (int hh = 0; hh < 8; hh++)
                wb[curb][hh] = Wg[(k0 + (kt+2)*8 + hh)*H + j];
        }
        #pragma unroll
        for (int hh = 0; hh < 8; hh++) {
            int hrel = kt*8 + hh;             // 0..127
            int cur = hrel & 1, nxt = cur ^ 1;
            int hnrel = (hrel + 1) & 127;     // wrap harmlessly at the end
            const ulonglong2* xp = (const ulonglong2*)(XT + (size_t)(k0 + hnrel)*XP);
            xs[nxt][0] = xp[0];
            xs[nxt][1] = xp[1];
            uint64_t w2 = pack2(w[hh], w[hh]);
            ffma2(acc[0], xs[cur][0].x, w2); ffma2(acc[1], xs[cur][0].y, w2);
            ffma2(acc[2], xs[cur][1].x, w2); ffma2(acc[3], xs[cur][1].y, w2);
        }
    }
}

// =============== prep: W = wq^T wk, biases folded, transposes ===============
__global__ void k_prep(const float* __restrict__ wq, const float* __restrict__ wk,
                       const float* __restrict__ bq, const float* __restrict__ bk,
                       const float* __restrict__ wv, const float* __restrict__ w1,
                       const float* __restrict__ w2) {
    int bidx = blockIdx.x;
    int j = threadIdx.x;
    if (bidx < H) {
        int h = bidx;
        __shared__ float s_wq[H];
        s_wq[j] = wq[j*H + h];
        __syncthreads();
        float acc = 0.f;
        #pragma unroll 4
        for (int m = 0; m < H; m++) acc += s_wq[m] * wk[m*H + j];
        g_W[h*H + j]   = acc;
        g_wvT[h*H + j] = wv[j*H + h];
        g_w1T[h*H + j] = w1[j*H + h];
        g_w2T[h*H + j] = w2[j*H + h];
    } else if (bidx == H) {
        float acc = 0.f;
        for (int m = 0; m < H; m++) acc += bq[m] * wk[m*H + j];
        g_btil[j] = acc;
    } else if (bidx == H + 1) {
        float acc = 0.f;
        for (int m = 0; m < H; m++) acc += wq[m*H + j] * bk[m];
        g_v[j] = acc;
    } else {
        if (j < 32) {
            float s = 0.f;
            for (int i = j; i < H; i += 32) s += bq[i] * bk[i];
            for (int off = 16; off; off >>= 1) s += __shfl_down_sync(0xffffffffu, s, off);
            if (j == 0) g_c0 = s;
        }
    }
}

// ========= Qtilde = target_h @ W + btil ; c = target_h . v + c0 =============
// 512 threads: thread = (col j = tid&255, khalf = tid>>8). 8 rows/block.
__global__ void __launch_bounds__(512) k_qtilde(const float* __restrict__ x) {
    __shared__ __align__(16) float s_x[H*XP];
    __shared__ float s_red[H*RP];
    __shared__ float s_part[16][4];
    int r0 = blockIdx.x * RB8;
    int tid = threadIdx.x;
    int j = tid & 255;
    int kh = tid >> 8;
    int k0 = kh << 7;
    int wid = tid >> 5, lane = tid & 31;

    // each k-half loads 4 of the 8 rows (coalesced) and stores transposed
    float v4[4];
    #pragma unroll
    for (int r = 0; r < 4; r++) v4[r] = x[(r0 + kh*4 + r)*H + j];
    *(float4*)&s_x[j*XP + kh*4] = make_float4(v4[0], v4[1], v4[2], v4[3]);

    // c partials: rows kh*4..+4 handled by this half's warps
    float gv = g_v[j];
    #pragma unroll
    for (int r = 0; r < 4; r++) {
        float s = v4[r] * gv;
        for (int off = 16; off; off >>= 1) s += __shfl_down_sync(0xffffffffu, s, off);
        if (lane == 0) s_part[wid][r] = s;
    }
    __syncthreads();
    if (tid < RB8) {
        int src = tid >> 2, rs = tid & 3;       // rows 0-3 from warps 0-7, 4-7 from 8-15
        float s = g_c0;
        #pragma unroll
        for (int w = 0; w < 8; w++) s += s_part[src*8 + w][rs];
        g_c[r0 + tid] = s;
    }

    uint64_t acc[4];
    float bt = (kh == 0) ? g_btil[j] : 0.f;
    #pragma unroll
    for (int i = 0; i < 4; i++) acc[i] = pack2(bt, bt);
    gemm8k(g_W, s_x, acc, j, k0);

    if (kh) {
        #pragma unroll
        for (int i = 0; i < 4; i++) {
            float lo, hi; unpack2(acc[i], lo, hi);
            s_red[j*RP + 2*i] = lo; s_red[j*RP + 2*i + 1] = hi;
        }
    }
    __syncthreads();
    if (!kh) {
        #pragma unroll
        for (int i = 0; i < 4; i++) {
            float lo, hi; unpack2(acc[i], lo, hi);
            g_Qt[(r0 + 2*i    )*H + j] = lo + s_red[j*RP + 2*i];
            g_Qt[(r0 + 2*i + 1)*H + j] = hi + s_red[j*RP + 2*i + 1];
        }
    }
}

// ===== k_logits (R2/R4 measured): logits, mask, top-8, softmax, aggregate ===
__global__ void k_logits(const float* __restrict__ peer,
                         const int* __restrict__ mask) {
    int bt = blockIdx.x;
    int b = bt >> 8;          // T = 256
    int t = bt & 255;
    __shared__ float qrow[H];
    __shared__ float lg[N*L];
    __shared__ float swt[TOPK];
    __shared__ int   sidx[TOPK];
    __shared__ float scbt;
    int tid = threadIdx.x;
    qrow[tid] = g_Qt[bt*H + tid];
    if (tid == 0) scbt = g_c[bt];
    __syncthreads();
    float cbt = scbt;
    int wid = tid >> 5, lane = tid & 31;
    const float4* q4 = (const float4*)qrow;

    for (int d = wid; d < N*L; d += 8) {
        int n = d / L, l = d - n*L;
        int tp = t - c_lags[l];
        bool ok = (tp >= 0) && (mask[(b << 6) + n] != 0);
        float val;
        if (ok) {
            const float4* p4 = (const float4*)(peer + ((size_t)((b*N + n)*T + tp)) * H);
            float s = 0.f;
            #pragma unroll
            for (int i = 0; i < 2; i++) {
                float4 pv = p4[lane + 32*i];
                float4 qv = q4[lane + 32*i];
                s += pv.x*qv.x + pv.y*qv.y + pv.z*qv.z + pv.w*qv.w;
            }
            for (int off = 16; off; off >>= 1) s += __shfl_down_sync(0xffffffffu, s, off);
            val = (s + cbt) * 0.0625f;
        } else {
            val = -INFINITY;
        }
        if (lane == 0) lg[d] = val;
    }
    __syncthreads();

    if (wid == 0) {
        float vals[TOPK];
        for (int k = 0; k < TOPK; k++) {
            float bv = -INFINITY; int bi = 0x7fffffff;
            for (int i = lane; i < N*L; i += 32) {
                float v = lg[i];
                if (v > bv || (v == bv && i < bi)) { bv = v; bi = i; }
            }
            for (int off = 16; off; off >>= 1) {
                float ov = __shfl_down_sync(0xffffffffu, bv, off);
                int   oi = __shfl_down_sync(0xffffffffu, bi, off);
                if (ov > bv || (ov == bv && oi < bi)) { bv = ov; bi = oi; }
            }
            bi = __shfl_sync(0xffffffffu, bi, 0);
            bv = __shfl_sync(0xffffffffu, bv, 0);
            if (lane == 0) { sidx[k] = bi; vals[k] = bv; lg[bi] = -INFINITY; }
            __syncwarp();
        }
        if (lane == 0) {
            float m = -INFINITY;
            bool allinf = true;
            float safe[TOPK];
            #pragma unroll
            for (int k = 0; k < TOPK; k++) {
                bool ii = isinf(vals[k]);
                allinf = allinf && ii;
                safe[k] = ii ? -1e9f : vals[k];
                if (safe[k] > m) m = safe[k];
            }
            float sw_ = 0.f;
            if (allinf) {
                #pragma unroll
                for (int k = 0; k < TOPK; k++) swt[k] = 0.f;
            } else {
                float e[TOPK]; float tot = 0.f;
                #pragma unroll
                for (int k = 0; k < TOPK; k++) { e[k] = expf(safe[k] - m); tot += e[k]; }
                #pragma unroll
                for (int k = 0; k < TOPK; k++) { float w = e[k] / tot; swt[k] = w; sw_ += w; }
            }
            g_sw[bt] = sw_;
        }
    }
    __syncthreads();

    float acc = 0.f;
    #pragma unroll
    for (int k = 0; k < TOPK; k++) {
        float w = swt[k];
        if (w != 0.f) {
            int d = sidx[k];
            int n = d / L, l = d - n*L;
            int tp = t - c_lags[l];
            acc += w * peer[((size_t)((b*N + n)*T + tp)) * H + tid];
        }
    }
    g_agg[bt*H + tid] = acc;
}

// ===== cs_y = agg@wv^T + sw*bv ; FFN(elu) ; residual ; LayerNorm ; out ======
// 512 threads, 8 rows/block, grid = 128. Thread = (col j, khalf).
__global__ void __launch_bounds__(512) k_ffn(
                      const float* __restrict__ bv, const float* __restrict__ b1,
                      const float* __restrict__ b2, const float* __restrict__ gamma,
                      const float* __restrict__ beta, float* __restrict__ out) {
    __shared__ __align__(16) float s_x[H*XP];     // transposed activations
    __shared__ float s_red[H*RP];                 // k-half reduction; reused as s_y
    __shared__ float s_sw[RB8];
    __shared__ float s_mu[RB8], s_rs[RB8];

    int r0 = blockIdx.x * RB8;
    int tid = threadIdx.x;
    int j = tid & 255;
    int kh = tid >> 8;
    int k0 = kh << 7;
    int wid = tid >> 5, lane = tid & 31;

    // each half loads 4 of the 8 agg rows (coalesced), stores transposed
    {
        float v4[4];
        #pragma unroll
        for (int r = 0; r < 4; r++) v4[r] = g_agg[(r0 + kh*4 + r)*H + j];
        *(float4*)&s_x[j*XP + kh*4] = make_float4(v4[0], v4[1], v4[2], v4[3]);
    }
    if (tid < RB8) s_sw[tid] = g_sw[r0 + tid];
    __syncthreads();

    // ---- GEMM1: cs = agg @ wv^T + sw*bv ----
    float cs[RB8];
    {
        uint64_t acc[4];
        float bvj = bv[j];
        if (kh == 0) {
            #pragma unroll
            for (int i = 0; i < 4; i++) acc[i] = pack2(s_sw[2*i]*bvj, s_sw[2*i+1]*bvj);
        } else {
            #pragma unroll
            for (int i = 0; i < 4; i++) acc[i] = pack2(0.f, 0.f);
        }
        gemm8k(g_wvT, s_x, acc, j, k0);
        if (kh) {
            #pragma unroll
            for (int i = 0; i < 4; i++)
                unpack2(acc[i], s_red[j*RP + 2*i], s_red[j*RP + 2*i + 1]);
        }
        __syncthreads();
        if (!kh) {
            #pragma unroll
            for (int i = 0; i < 4; i++) {
                float lo, hi; unpack2(acc[i], lo, hi);
                cs[2*i]   = lo + s_red[j*RP + 2*i];
                cs[2*i+1] = hi + s_red[j*RP + 2*i + 1];
            }
            *(float4*)&s_x[j*XP]     = make_float4(cs[0], cs[1], cs[2], cs[3]);
            *(float4*)&s_x[j*XP + 4] = make_float4(cs[4], cs[5], cs[6], cs[7]);
        }
        __syncthreads();
    }

    // ---- GEMM2: hidden = elu(cs @ w1^T + b1) ----
    {
        uint64_t acc[4];
        float b1j = (kh == 0) ? b1[j] : 0.f;
        #pragma unroll
        for (int i = 0; i < 4; i++) acc[i] = pack2(b1j, b1j);
        gemm8k(g_w1T, s_x, acc, j, k0);
        if (kh) {
            #pragma unroll
            for (int i = 0; i < 4; i++)
                unpack2(acc[i], s_red[j*RP + 2*i], s_red[j*RP + 2*i + 1]);
        }
        __syncthreads();
        if (!kh) {
            float hd[RB8];
            #pragma unroll
            for (int i = 0; i < 4; i++) {
                float lo, hi; unpack2(acc[i], lo, hi);
                hd[2*i]   = lo + s_red[j*RP + 2*i];
                hd[2*i+1] = hi + s_red[j*RP + 2*i + 1];
            }
            #pragma unroll
            for (int r = 0; r < RB8; r++) hd[r] = hd[r] > 0.f ? hd[r] : expm1f(hd[r]);
            *(float4*)&s_x[j*XP]     = make_float4(hd[0], hd[1], hd[2], hd[3]);
            *(float4*)&s_x[j*XP + 4] = make_float4(hd[4], hd[5], hd[6], hd[7]);
        }
        __syncthreads();
    }

    // ---- GEMM3: y = cs + hidden @ w2^T + b2 ----
    float y[RB8];
    {
        uint64_t acc[4];
        if (kh == 0) {
            float b2j = b2[j];
            #pragma unroll
            for (int i = 0; i < 4; i++) acc[i] = pack2(b2j + cs[2*i], b2j + cs[2*i+1]);
        } else {
            #pragma unroll
            for (int i = 0; i < 4; i++) acc[i] = pack2(0.f, 0.f);
        }
        gemm8k(g_w2T, s_x, acc, j, k0);
        if (kh) {
            #pragma unroll
            for (int i = 0; i < 4; i++)
                unpack2(acc[i], s_red[j*RP + 2*i], s_red[j*RP + 2*i + 1]);
        }
        __syncthreads();
        if (!kh) {
            #pragma unroll
            for (int i = 0; i < 4; i++) {
                float lo, hi; unpack2(acc[i], lo, hi);
                y[2*i]   = lo + s_red[j*RP + 2*i];
                y[2*i+1] = hi + s_red[j*RP + 2*i + 1];
            }
        }
        __syncthreads();        // s_red reads done before reuse as s_y
    }

    // ---- LayerNorm: y stashed into s_red as [r][256], warps 0-7 reduce ----
    float* s_y = s_red;
    if (!kh) {
        #pragma unroll
        for (int r = 0; r < RB8; r++) s_y[r*H + j] = y[r];
    }
    __syncthreads();
    if (wid < 8) {              // kh==0 warps
        int r = wid;
        float s = 0.f, q = 0.f;
        #pragma unroll
        for (int k = 0; k < 8; k++) {
            float vv = s_y[r*H + lane + 32*k];
            s += vv; q += vv*vv;
        }
        for (int off = 16; off; off >>= 1) {
            s += __shfl_down_sync(0xffffffffu, s, off);
            q += __shfl_down_sync(0xffffffffu, q, off);
        }
        if (lane == 0) {
            float mu = s * (1.f/H);
            float var = q * (1.f/H) - mu*mu;
            s_mu[r] = mu;
            s_rs[r] = rsqrtf(var + 1e-5f);
        }
    }
    __syncthreads();
    if (!kh) {
        float gj = gamma[j], bj = beta[j];
        #pragma unroll
        for (int r = 0; r < RB8; r++)
            out[(r0 + r)*H + j] = (y[r] - s_mu[r]) * s_rs[r] * gj + bj;
    }
}

extern "C" void kernel_launch(void* const* d_in, const int* in_sizes, int n_in,
                              void* d_out, int out_size) {
    const float* target_h = (const float*)d_in[0];
    const float* peer_h   = (const float*)d_in[1];
    const int*   peer_mask = (const int*)d_in[2];
    const float* wq = (const float*)d_in[3];
    const float* bq = (const float*)d_in[4];
    const float* wk = (const float*)d_in[5];
    const float* bk = (const float*)d_in[6];
    const float* wv = (const float*)d_in[7];
    const float* bv = (const float*)d_in[8];
    const float* w1 = (const float*)d_in[9];
    const float* b1 = (const float*)d_in[10];
    const float* w2 = (const float*)d_in[11];
    const float* b2 = (const float*)d_in[12];
    const float* gamma = (const float*)d_in[13];
    const float* beta  = (const float*)d_in[14];
    float* out = (float*)d_out;

    k_prep<<<H + 3, 256>>>(wq, wk, bq, bk, wv, w1, w2);
    k_qtilde<<<BT/RB8, 512>>>(target_h);
    k_logits<<<BT, 256>>>(peer_h, peer_mask);
    k_ffn<<<BT/RB8, 512>>>(bv, b1, b2, gamma, beta, out);
}